// round 1
// baseline (speedup 1.0000x reference)
#include <cuda_runtime.h>
#include <math.h>

// Sinkhorn approximate EMD: B=8, N=2048, 3-D points, 50 iterations.
// Strategy: materialize K and K^T once in __device__ scratch (268 MB),
// run 100 HBM-bound matvec+update kernels, deterministic two-stage epilogue.

#define BB 8
#define NN 2048
#define TPB 256
#define LOGN_SHIFT 11   // NN == 1 << 11

__device__ float g_K [(size_t)BB * NN * NN];   // K[b,i,j]  = exp(-100*||x1_i - x2_j||^2)
__device__ float g_KT[(size_t)BB * NN * NN];   // KT[b,j,i] = K[b,i,j]
__device__ float g_u   [BB * NN];
__device__ float g_v   [BB * NN];
__device__ float g_expu[BB * NN];
__device__ float g_expv[BB * NN];
__device__ float g_part[BB * NN];

// ---------------------------------------------------------------------------
__global__ void init_expv_kernel() {
    int i = blockIdx.x * blockDim.x + threadIdx.x;
    if (i < BB * NN) g_expv[i] = 1.0f;   // v0 = 0 -> exp(v0) = 1
}

// ---------------------------------------------------------------------------
// Build K (toT=0) or K^T (toT=1, by swapping xa/xb at the call site).
// One block per (b, row). xb batch staged in smem (24 KB).
__global__ void kgen_kernel(const float* __restrict__ xa,
                            const float* __restrict__ xb, int toT) {
    __shared__ float sx[NN * 3];
    int b = blockIdx.x >> LOGN_SHIFT;
    int r = blockIdx.x & (NN - 1);

    const float* xbp = xb + (size_t)b * NN * 3;
    for (int t = threadIdx.x; t < NN * 3; t += TPB) sx[t] = xbp[t];
    __syncthreads();

    const float* ap = xa + ((size_t)b * NN + r) * 3;
    float ax = ap[0], ay = ap[1], az = ap[2];

    float* orow = (toT ? g_KT : g_K) + ((size_t)b * NN + r) * NN;
    #pragma unroll 4
    for (int c = threadIdx.x; c < NN; c += TPB) {
        float dx = ax - sx[3 * c];
        float dy = ay - sx[3 * c + 1];
        float dz = az - sx[3 * c + 2];
        float d2 = fmaf(dx, dx, fmaf(dy, dy, dz * dz));
        orow[c] = __expf(-100.0f * d2);
    }
}

// ---------------------------------------------------------------------------
__device__ __forceinline__ float block_reduce_256(float v) {
    __shared__ float red[8];
    int lane = threadIdx.x & 31;
    int w    = threadIdx.x >> 5;
    #pragma unroll
    for (int o = 16; o; o >>= 1) v += __shfl_down_sync(0xffffffffu, v, o);
    if (lane == 0) red[w] = v;
    __syncthreads();
    if (w == 0) {
        v = (lane < 8) ? red[lane] : 0.0f;
        #pragma unroll
        for (int o = 4; o; o >>= 1) v += __shfl_down_sync(0xffffffffu, v, o);
    }
    return v;   // valid on thread 0
}

// ---------------------------------------------------------------------------
// One half-iteration. phase=0: u = log_mu - log(K @ exp(v) + eps)
//                     phase=1: v = log_nu - log(K^T @ exp(u) + eps)
// One block per (b, row); float4 loads; row (8 KB) from HBM, evec (8 KB) from L2.
__global__ void sink_update_kernel(int phase, float logmass) {
    int b = blockIdx.x >> LOGN_SHIFT;
    int r = blockIdx.x & (NN - 1);

    const float*  Kmat = phase ? g_KT : g_K;
    const float*  evec = (phase ? g_expu : g_expv) + b * NN;
    const float4* krow = (const float4*)(Kmat + ((size_t)b * NN + r) * NN);
    const float4* ev4  = (const float4*)evec;

    int t = threadIdx.x;
    float4 k0 = krow[t];
    float4 e0 = ev4[t];
    float4 k1 = krow[t + TPB];
    float4 e1 = ev4[t + TPB];

    float s = k0.x * e0.x + k0.y * e0.y + k0.z * e0.z + k0.w * e0.w
            + k1.x * e1.x + k1.y * e1.y + k1.z * e1.z + k1.w * e1.w;

    s = block_reduce_256(s);

    if (t == 0) {
        float lv = logmass - __logf(s + 1e-8f);
        float ev = __expf(lv);
        int idx = b * NN + r;
        if (phase) { g_v[idx] = lv; g_expv[idx] = ev; }
        else       { g_u[idx] = lv; g_expu[idx] = ev; }
    }
}

// ---------------------------------------------------------------------------
// Per-row partial of sum_ij K_ij * exp(u_i + v_j) * cost_ij.
// cost recomputed from points (cheap); skip exp when K underflowed to 0.
__global__ void emd_partial_kernel(const float* __restrict__ x1,
                                   const float* __restrict__ x2) {
    __shared__ float sx[NN * 3];
    int b = blockIdx.x >> LOGN_SHIFT;
    int r = blockIdx.x & (NN - 1);

    const float* xbp = x2 + (size_t)b * NN * 3;
    for (int t = threadIdx.x; t < NN * 3; t += TPB) sx[t] = xbp[t];
    __syncthreads();

    const float* ap = x1 + ((size_t)b * NN + r) * 3;
    float ax = ap[0], ay = ap[1], az = ap[2];
    float ui = g_u[b * NN + r];

    const float* krow = g_K + ((size_t)b * NN + r) * NN;
    const float* vb   = g_v + b * NN;

    float s = 0.0f;
    for (int c = threadIdx.x; c < NN; c += TPB) {
        float kv = krow[c];
        if (kv != 0.0f) {
            float dx = ax - sx[3 * c];
            float dy = ay - sx[3 * c + 1];
            float dz = az - sx[3 * c + 2];
            float d2 = fmaf(dx, dx, fmaf(dy, dy, dz * dz));
            s += kv * __expf(ui + vb[c]) * d2;
        }
    }
    s = block_reduce_256(s);
    if (threadIdx.x == 0) g_part[b * NN + r] = s;
}

__global__ void emd_final_kernel(float* __restrict__ out) {
    int b = blockIdx.x;
    float s = 0.0f;
    for (int i = threadIdx.x; i < NN; i += TPB) s += g_part[b * NN + i];
    s = block_reduce_256(s);
    if (threadIdx.x == 0) out[b] = s;
}

// ---------------------------------------------------------------------------
extern "C" void kernel_launch(void* const* d_in, const int* in_sizes, int n_in,
                              void* d_out, int out_size) {
    (void)in_sizes; (void)n_in; (void)out_size;
    const float* x1 = (const float*)d_in[0];
    const float* x2 = (const float*)d_in[1];
    float* out = (float*)d_out;

    const float logm = logf(1.0f / 2048.0f + 1e-8f);  // log_mu == log_nu

    init_expv_kernel<<<(BB * NN + TPB - 1) / TPB, TPB>>>();
    kgen_kernel<<<BB * NN, TPB>>>(x1, x2, 0);   // K
    kgen_kernel<<<BB * NN, TPB>>>(x2, x1, 1);   // K^T

    for (int it = 0; it < 50; ++it) {
        sink_update_kernel<<<BB * NN, TPB>>>(0, logm);  // u update
        sink_update_kernel<<<BB * NN, TPB>>>(1, logm);  // v update
    }

    emd_partial_kernel<<<BB * NN, TPB>>>(x1, x2);
    emd_final_kernel<<<BB, TPB>>>(out);
}

// round 2
// speedup vs baseline: 3.3786x; 3.3786x over previous
#include <cuda_runtime.h>
#include <math.h>

// Sinkhorn approximate EMD: B=8, N=2048, 3D points, 50 iterations.
// R2: sparse CSR K / K^T (entries with exp(-100 d^2) >= 1e-30, ~4.5% density,
// ~18 MB total -> L2-resident). 100 sparse matvec launches replace the
// HBM-bound dense passes. Deterministic fixed-order reductions throughout.

#define BB 8
#define NN 2048
#define NROWS (BB * NN)          // 16384
#define RPB 16                   // rows per block
#define TPB 512                  // 16 warps
#define LOGN_SHIFT 11
#define CAP (1u << 24)           // 16.7M entries/matrix (~50% density headroom)
#define D2CUT 0.690776f          // -ln(1e-30)/100

__device__ float          g_vals[2][CAP];
__device__ unsigned short g_cols[2][CAP];
__device__ unsigned       g_cnt[2][NROWS];
__device__ unsigned       g_rowptr[2][NROWS + 1];
__device__ float g_u[NROWS], g_v[NROWS], g_expu[NROWS], g_expv[NROWS], g_part[NROWS];

// ---------------------------------------------------------------------------
__global__ void init_expv_kernel() {
    int i = blockIdx.x * blockDim.x + threadIdx.x;
    if (i < NROWS) g_expv[i] = 1.0f;      // v0 = 0 -> exp(v0) = 1
}

// ---------------------------------------------------------------------------
// Count nonzeros per row of matrix m (m=0: K rows=x1, m=1: K^T rows=x2).
__global__ void count_kernel(const float* __restrict__ xa,
                             const float* __restrict__ xb, int m) {
    __shared__ float sx[NN * 3];
    int b = (blockIdx.x * RPB) >> LOGN_SHIFT;
    const float* xbp = xb + (size_t)b * NN * 3;
    for (int t = threadIdx.x; t < NN * 3; t += TPB) sx[t] = xbp[t];
    __syncthreads();

    int warp = threadIdx.x >> 5, lane = threadIdx.x & 31;
    int row  = blockIdx.x * RPB + warp;
    const float* ap = xa + (size_t)row * 3;
    float ax = ap[0], ay = ap[1], az = ap[2];

    unsigned cnt = 0;
    for (int c = lane; c < NN; c += 32) {
        float dx = ax - sx[3 * c];
        float dy = ay - sx[3 * c + 1];
        float dz = az - sx[3 * c + 2];
        float d2 = fmaf(dx, dx, fmaf(dy, dy, dz * dz));
        cnt += (d2 < D2CUT);
    }
    cnt = __reduce_add_sync(0xffffffffu, cnt);
    if (lane == 0) g_cnt[m][row] = cnt;
}

// ---------------------------------------------------------------------------
// Single-block exclusive scan of 16384 counts -> row pointers.
__global__ void scan_kernel(int m) {
    __shared__ unsigned part[1024];
    int t = threadIdx.x;
    unsigned local[16];
    unsigned s = 0;
    #pragma unroll
    for (int k = 0; k < 16; k++) { local[k] = s; s += g_cnt[m][t * 16 + k]; }
    part[t] = s;
    __syncthreads();
    for (int off = 1; off < 1024; off <<= 1) {
        unsigned v = (t >= off) ? part[t - off] : 0u;
        __syncthreads();
        part[t] += v;
        __syncthreads();
    }
    unsigned base = t ? part[t - 1] : 0u;
    #pragma unroll
    for (int k = 0; k < 16; k++) g_rowptr[m][t * 16 + k] = base + local[k];
    if (t == 1023) g_rowptr[m][NROWS] = part[1023];
}

// ---------------------------------------------------------------------------
// Fill CSR values/cols via warp ballot compaction.
__global__ void fill_kernel(const float* __restrict__ xa,
                            const float* __restrict__ xb, int m) {
    __shared__ float sx[NN * 3];
    int b = (blockIdx.x * RPB) >> LOGN_SHIFT;
    const float* xbp = xb + (size_t)b * NN * 3;
    for (int t = threadIdx.x; t < NN * 3; t += TPB) sx[t] = xbp[t];
    __syncthreads();

    int warp = threadIdx.x >> 5, lane = threadIdx.x & 31;
    int row  = blockIdx.x * RPB + warp;
    const float* ap = xa + (size_t)row * 3;
    float ax = ap[0], ay = ap[1], az = ap[2];

    unsigned base = g_rowptr[m][row];
    for (int c0 = 0; c0 < NN; c0 += 32) {
        int c = c0 + lane;
        float dx = ax - sx[3 * c];
        float dy = ay - sx[3 * c + 1];
        float dz = az - sx[3 * c + 2];
        float d2 = fmaf(dx, dx, fmaf(dy, dy, dz * dz));
        bool p = d2 < D2CUT;
        unsigned mk = __ballot_sync(0xffffffffu, p);
        if (p) {
            unsigned idx = base + __popc(mk & ((1u << lane) - 1u));
            if (idx < CAP) {
                g_vals[m][idx] = __expf(-100.0f * d2);
                g_cols[m][idx] = (unsigned short)c;
            }
        }
        base += __popc(mk);
    }
}

// ---------------------------------------------------------------------------
// One Sinkhorn half-iteration on the sparse matrix. One warp per row.
// phase=0: u = logm - log(K @ exp(v) + eps);  phase=1: v via K^T @ exp(u).
__global__ void sink_sparse_kernel(int phase, float logm) {
    __shared__ float sev[NN];
    int b = (blockIdx.x * RPB) >> LOGN_SHIFT;
    const float* evec = (phase ? g_expu : g_expv) + b * NN;
    ((float4*)sev)[threadIdx.x] = ((const float4*)evec)[threadIdx.x];  // 512*4 = 2048
    __syncthreads();

    int warp = threadIdx.x >> 5, lane = threadIdx.x & 31;
    int row  = blockIdx.x * RPB + warp;
    int m = phase;
    unsigned s0 = g_rowptr[m][row], s1 = g_rowptr[m][row + 1];

    float acc = 0.0f;
    for (unsigned k = s0 + lane; k < s1; k += 32)
        acc += g_vals[m][k] * sev[g_cols[m][k]];

    #pragma unroll
    for (int o = 16; o; o >>= 1) acc += __shfl_down_sync(0xffffffffu, acc, o);

    if (lane == 0) {
        float lv = logm - __logf(acc + 1e-8f);
        float ev = __expf(lv);
        if (phase) { g_v[row] = lv; g_expv[row] = ev; }
        else       { g_u[row] = lv; g_expu[row] = ev; }
    }
}

// ---------------------------------------------------------------------------
// Per-row partial of sum_j K_ij * expu_i * expv_j * d2_ij (cost recomputed).
__global__ void emd_partial_kernel(const float* __restrict__ x1,
                                   const float* __restrict__ x2) {
    __shared__ float sx[NN * 3];
    __shared__ float sev[NN];
    int b = (blockIdx.x * RPB) >> LOGN_SHIFT;
    const float* xbp = x2 + (size_t)b * NN * 3;
    for (int t = threadIdx.x; t < NN * 3; t += TPB) sx[t] = xbp[t];
    ((float4*)sev)[threadIdx.x] = ((const float4*)(g_expv + b * NN))[threadIdx.x];
    __syncthreads();

    int warp = threadIdx.x >> 5, lane = threadIdx.x & 31;
    int row  = blockIdx.x * RPB + warp;
    const float* ap = x1 + (size_t)row * 3;
    float ax = ap[0], ay = ap[1], az = ap[2];
    float eu = g_expu[row];

    unsigned s0 = g_rowptr[0][row], s1 = g_rowptr[0][row + 1];
    float acc = 0.0f;
    for (unsigned k = s0 + lane; k < s1; k += 32) {
        int c = g_cols[0][k];
        float dx = ax - sx[3 * c];
        float dy = ay - sx[3 * c + 1];
        float dz = az - sx[3 * c + 2];
        float d2 = fmaf(dx, dx, fmaf(dy, dy, dz * dz));
        acc += g_vals[0][k] * eu * sev[c] * d2;
    }
    #pragma unroll
    for (int o = 16; o; o >>= 1) acc += __shfl_down_sync(0xffffffffu, acc, o);
    if (lane == 0) g_part[row] = acc;
}

// ---------------------------------------------------------------------------
__global__ void emd_final_kernel(float* __restrict__ out) {
    __shared__ float red[16];
    int b = blockIdx.x;
    float s = 0.0f;
    for (int i = threadIdx.x; i < NN; i += TPB) s += g_part[b * NN + i];
    int lane = threadIdx.x & 31, w = threadIdx.x >> 5;
    #pragma unroll
    for (int o = 16; o; o >>= 1) s += __shfl_down_sync(0xffffffffu, s, o);
    if (lane == 0) red[w] = s;
    __syncthreads();
    if (w == 0) {
        s = (lane < 16) ? red[lane] : 0.0f;
        #pragma unroll
        for (int o = 8; o; o >>= 1) s += __shfl_down_sync(0xffffffffu, s, o);
        if (lane == 0) out[b] = s;
    }
}

// ---------------------------------------------------------------------------
extern "C" void kernel_launch(void* const* d_in, const int* in_sizes, int n_in,
                              void* d_out, int out_size) {
    (void)in_sizes; (void)n_in; (void)out_size;
    const float* x1 = (const float*)d_in[0];
    const float* x2 = (const float*)d_in[1];
    float* out = (float*)d_out;

    const float logm = logf(1.0f / 2048.0f + 1e-8f);
    const int NBLK = NROWS / RPB;   // 1024

    init_expv_kernel<<<NROWS / TPB, TPB>>>();
    count_kernel<<<NBLK, TPB>>>(x1, x2, 0);   // K   rows = x1 points
    count_kernel<<<NBLK, TPB>>>(x2, x1, 1);   // K^T rows = x2 points
    scan_kernel<<<1, 1024>>>(0);
    scan_kernel<<<1, 1024>>>(1);
    fill_kernel<<<NBLK, TPB>>>(x1, x2, 0);
    fill_kernel<<<NBLK, TPB>>>(x2, x1, 1);

    for (int it = 0; it < 50; ++it) {
        sink_sparse_kernel<<<NBLK, TPB>>>(0, logm);   // u update
        sink_sparse_kernel<<<NBLK, TPB>>>(1, logm);   // v update
    }

    emd_partial_kernel<<<NBLK, TPB>>>(x1, x2);
    emd_final_kernel<<<BB, TPB>>>(out);
}